// round 1
// baseline (speedup 1.0000x reference)
#include <cuda_runtime.h>
#include <cstdint>

// Problem constants (fixed by the reference setup)
constexpr int HIDDEN = 1024;
constexpr int INTER  = 1408;
constexpr int NEXP   = 8;
constexpr int TOKENS = 8192;

// Scratch: __device__ globals (no allocation allowed in kernel_launch).
// gate_up: [TOKENS, 2*INTER] = 92.3 MB ; h: [TOKENS, INTER] = 46.2 MB
__device__ __align__(128) float g_gateup[(size_t)TOKENS * 2 * INTER];
__device__ __align__(128) float g_h[(size_t)TOKENS * INTER];

// tokens_per_expert may arrive as int32 or int64 (np.int64 -> jnp downcast
// is config-dependent). Detect on device: the int32 reading sums to TOKENS
// iff the buffer really is int32.
__device__ __forceinline__ void load_offsets(const void* tpe_ptr, int e,
                                             int& off, int& cnt) {
    const int* p32 = (const int*)tpe_ptr;
    int s = 0;
#pragma unroll
    for (int i = 0; i < NEXP; i++) s += p32[i];
    off = 0; cnt = 0;
    if (s == TOKENS) {
#pragma unroll
        for (int i = 0; i < NEXP; i++) {
            int v = p32[i];
            if (i < e)  off += v;
            if (i == e) cnt = v;
        }
    } else {
        const long long* p64 = (const long long*)tpe_ptr;
#pragma unroll
        for (int i = 0; i < NEXP; i++) {
            int v = (int)p64[i];
            if (i < e)  off += v;
            if (i == e) cnt = v;
        }
    }
}

// Grouped SGEMM: C[off:off+cnt, :] = A[off:off+cnt, :K] @ W[e]  (W[e]: [K, N])
// Tokens are contiguous per expert. Tile: BM=BN=128, BK=8, 256 threads,
// 8x8 register tile per thread. Ragged M handled with guards; N, K are
// multiples of 128 / 8 for all three uses.
__global__ __launch_bounds__(256) void grouped_sgemm(
    const float* __restrict__ A,   // [TOKENS, K]
    const float* __restrict__ W,   // [NEXP, K, N]
    float* __restrict__ C,         // [TOKENS, N]
    const void* __restrict__ tpe_ptr,
    int K, int N)
{
    const int e = blockIdx.z;
    int off, cnt;
    load_offsets(tpe_ptr, e, off, cnt);

    const int m0 = blockIdx.y * 128;
    if (m0 >= cnt) return;            // over-launched m-slot for this expert
    const int n0 = blockIdx.x * 128;

    const float* Ae = A + (size_t)off * K;
    const float* We = W + (size_t)e * K * N;
    float*       Ce = C + (size_t)off * N;

    __shared__ float As[8][128];      // transposed A tile: As[k][m]
    __shared__ float Bs[8][128];      // B tile: Bs[k][n]

    const int tid = threadIdx.x;
    const int tx  = tid & 15;         // n-direction (0..15)
    const int ty  = tid >> 4;         // m-direction (0..15)

    // Cooperative load indices (one float4 per thread per tile)
    const int a_row = tid >> 1;          // 0..127
    const int a_col = (tid & 1) * 4;     // 0 or 4
    const int b_row = tid >> 5;          // 0..7
    const int b_col = (tid & 31) * 4;    // 0..124

    float acc[8][8];
#pragma unroll
    for (int i = 0; i < 8; i++)
#pragma unroll
        for (int j = 0; j < 8; j++) acc[i][j] = 0.0f;

    for (int k0 = 0; k0 < K; k0 += 8) {
        // Load A tile (guard ragged rows; zero-fill OOB so math is exact)
        float4 av = make_float4(0.f, 0.f, 0.f, 0.f);
        if (m0 + a_row < cnt)
            av = *(const float4*)&Ae[(size_t)(m0 + a_row) * K + k0 + a_col];
        As[a_col + 0][a_row] = av.x;
        As[a_col + 1][a_row] = av.y;
        As[a_col + 2][a_row] = av.z;
        As[a_col + 3][a_row] = av.w;

        // Load B tile (always in-bounds: N, K exact multiples)
        *(float4*)&Bs[b_row][b_col] =
            *(const float4*)&We[(size_t)(k0 + b_row) * N + n0 + b_col];

        __syncthreads();

#pragma unroll
        for (int kk = 0; kk < 8; kk++) {
            float a[8], b[8];
            *(float4*)&a[0] = *(const float4*)&As[kk][ty * 8];
            *(float4*)&a[4] = *(const float4*)&As[kk][ty * 8 + 4];
            *(float4*)&b[0] = *(const float4*)&Bs[kk][tx * 8];
            *(float4*)&b[4] = *(const float4*)&Bs[kk][tx * 8 + 4];
#pragma unroll
            for (int i = 0; i < 8; i++)
#pragma unroll
                for (int j = 0; j < 8; j++)
                    acc[i][j] = fmaf(a[i], b[j], acc[i][j]);
        }
        __syncthreads();
    }

    // Store 8x8 tile (guard ragged rows)
#pragma unroll
    for (int i = 0; i < 8; i++) {
        int row = m0 + ty * 8 + i;
        if (row < cnt) {
            float* dst = &Ce[(size_t)row * N + n0 + tx * 8];
            *(float4*)(dst)     = *(float4*)&acc[i][0];
            *(float4*)(dst + 4) = *(float4*)&acc[i][4];
        }
    }
}

// swiglu: h[t, c] = silu(gate_up[t, c]) * gate_up[t, c + INTER]
__global__ __launch_bounds__(256) void swiglu_kernel(
    const float* __restrict__ gup, float* __restrict__ h)
{
    int i = blockIdx.x * blockDim.x + threadIdx.x;
    const int total = TOKENS * INTER;
    if (i >= total) return;
    int t = i / INTER;
    int c = i - t * INTER;
    const float* row = gup + (size_t)t * (2 * INTER);
    float gate = row[c];
    float up   = row[c + INTER];
    float s = gate / (1.0f + __expf(-gate));
    h[i] = s * up;
}

extern "C" void kernel_launch(void* const* d_in, const int* in_sizes, int n_in,
                              void* d_out, int out_size) {
    const float* x    = (const float*)d_in[0];   // [8192, 1024]
    const float* w1w3 = (const float*)d_in[1];   // [8, 1024, 2816]
    const float* w2   = (const float*)d_in[2];   // [8, 1408, 1024]
    const void*  tpe  = d_in[3];                 // [8] int32 or int64
    float* out = (float*)d_out;                  // [8192, 1024]

    float *gup, *h;
    cudaGetSymbolAddress((void**)&gup, g_gateup);
    cudaGetSymbolAddress((void**)&h,   g_h);

    dim3 blk(256);

    // GEMM1: gate_up = x @ w1w3[e]   (K=1024, N=2816)
    dim3 g1((2 * INTER) / 128, TOKENS / 128, NEXP);   // (22, 64, 8)
    grouped_sgemm<<<g1, blk>>>(x, w1w3, gup, tpe, HIDDEN, 2 * INTER);

    // swiglu
    int total = TOKENS * INTER;
    swiglu_kernel<<<(total + 255) / 256, blk>>>(gup, h);

    // GEMM2: out = h @ w2[e]   (K=1408, N=1024)
    dim3 g2(HIDDEN / 128, TOKENS / 128, NEXP);        // (8, 64, 8)
    grouped_sgemm<<<g2, blk>>>(h, w2, out, tpe, INTER, HIDDEN);
}

// round 3
// speedup vs baseline: 2.7899x; 2.7899x over previous
#include <cuda_runtime.h>
#include <cuda_bf16.h>
#include <cstdint>

using bf16 = __nv_bfloat16;

constexpr int HIDDEN = 1024;
constexpr int INTER  = 1408;
constexpr int NEXP   = 8;
constexpr int TOKENS = 8192;

// ---------------- scratch (device globals; no allocation allowed) ----------
__device__ __align__(256) bf16 g_xh[(size_t)TOKENS * HIDDEN];
__device__ __align__(256) bf16 g_xl[(size_t)TOKENS * HIDDEN];
__device__ __align__(256) bf16 g_w1h[(size_t)NEXP * 2 * INTER * HIDDEN]; // [E][N=2816][K=1024]
__device__ __align__(256) bf16 g_w1l[(size_t)NEXP * 2 * INTER * HIDDEN];
__device__ __align__(256) bf16 g_w2h[(size_t)NEXP * HIDDEN * INTER];     // [E][N=1024][K=1408]
__device__ __align__(256) bf16 g_w2l[(size_t)NEXP * HIDDEN * INTER];
__device__ __align__(256) bf16 g_hh[(size_t)TOKENS * INTER];
__device__ __align__(256) bf16 g_hl[(size_t)TOKENS * INTER];

// ---------------- helpers ---------------------------------------------------
__device__ __forceinline__ void load_offsets(const void* tpe_ptr, int e,
                                             int& off, int& cnt) {
    const int* p32 = (const int*)tpe_ptr;
    int s = 0;
#pragma unroll
    for (int i = 0; i < NEXP; i++) s += p32[i];
    off = 0; cnt = 0;
    if (s == TOKENS) {
#pragma unroll
        for (int i = 0; i < NEXP; i++) {
            int v = p32[i];
            if (i < e)  off += v;
            if (i == e) cnt = v;
        }
    } else {
        const long long* p64 = (const long long*)tpe_ptr;
#pragma unroll
        for (int i = 0; i < NEXP; i++) {
            int v = (int)p64[i];
            if (i < e)  off += v;
            if (i == e) cnt = v;
        }
    }
}

__device__ __forceinline__ uint32_t smem_u32(const void* p) {
    uint32_t a;
    asm("{ .reg .u64 t; cvta.to.shared.u64 t, %1; cvt.u32.u64 %0, t; }"
        : "=r"(a) : "l"(p));
    return a;
}

#define SW128(o) ((o) ^ (((o) >> 3) & 0x70))

__device__ __forceinline__ void cp16(uint32_t s, const void* g, int nbytes) {
    asm volatile("cp.async.cg.shared.global [%0], [%1], 16, %2;"
                 :: "r"(s), "l"(g), "r"(nbytes) : "memory");
}

__device__ __forceinline__ void ldmx4(uint32_t* r, uint32_t addr) {
    asm volatile("ldmatrix.sync.aligned.m8n8.x4.shared.b16 {%0,%1,%2,%3}, [%4];"
                 : "=r"(r[0]), "=r"(r[1]), "=r"(r[2]), "=r"(r[3]) : "r"(addr));
}

__device__ __forceinline__ void mma16816(float* c, const uint32_t* a, const uint32_t* b) {
    asm volatile("mma.sync.aligned.m16n8k16.row.col.f32.bf16.bf16.f32 "
                 "{%0,%1,%2,%3}, {%4,%5,%6,%7}, {%8,%9}, {%0,%1,%2,%3};"
                 : "+f"(c[0]), "+f"(c[1]), "+f"(c[2]), "+f"(c[3])
                 : "r"(a[0]), "r"(a[1]), "r"(a[2]), "r"(a[3]),
                   "r"(b[0]), "r"(b[1]));
}

__device__ __forceinline__ void split_bf16(float v, unsigned short& h, unsigned short& l) {
    bf16 hb = __float2bfloat16(v);
    bf16 lb = __float2bfloat16(v - __bfloat162float(hb));
    h = __bfloat16_as_ushort(hb);
    l = __bfloat16_as_ushort(lb);
}

// ---------------- conversion kernels ---------------------------------------
__global__ __launch_bounds__(256) void convert_split(
    const float* __restrict__ src, bf16* __restrict__ dh, bf16* __restrict__ dl, int n4)
{
    int i = blockIdx.x * 256 + threadIdx.x;
    if (i >= n4) return;
    float4 v = ((const float4*)src)[i];
    float vv[4] = {v.x, v.y, v.z, v.w};
    unsigned short hh[4], ll[4];
#pragma unroll
    for (int j = 0; j < 4; j++) split_bf16(vv[j], hh[j], ll[j]);
    uint2 ph = make_uint2((uint32_t)hh[0] | ((uint32_t)hh[1] << 16),
                          (uint32_t)hh[2] | ((uint32_t)hh[3] << 16));
    uint2 pl = make_uint2((uint32_t)ll[0] | ((uint32_t)ll[1] << 16),
                          (uint32_t)ll[2] | ((uint32_t)ll[3] << 16));
    ((uint2*)dh)[i] = ph;
    ((uint2*)dl)[i] = pl;
}

// transpose + split: src [E][K][N] f32 -> dst [E][N][K] bf16 (hi, lo)
__global__ __launch_bounds__(256) void convert_split_t(
    const float* __restrict__ src, bf16* __restrict__ dh, bf16* __restrict__ dl,
    int K, int N)
{
    __shared__ unsigned short sh[32][33], sl[32][33];
    const float* S = src + (size_t)blockIdx.z * K * N;
    bf16* DH = dh + (size_t)blockIdx.z * K * N;
    bf16* DL = dl + (size_t)blockIdx.z * K * N;
    int n0 = blockIdx.x * 32, k0 = blockIdx.y * 32;
    int tx = threadIdx.x & 31, ty = threadIdx.x >> 5;
#pragma unroll
    for (int r = ty; r < 32; r += 8) {
        float v = S[(size_t)(k0 + r) * N + n0 + tx];
        split_bf16(v, sh[tx][r], sl[tx][r]);
    }
    __syncthreads();
    int kp = threadIdx.x & 15, nyb = threadIdx.x >> 4;
#pragma unroll
    for (int ny = nyb; ny < 32; ny += 16) {
        uint32_t ph = (uint32_t)sh[ny][2 * kp] | ((uint32_t)sh[ny][2 * kp + 1] << 16);
        uint32_t pl = (uint32_t)sl[ny][2 * kp] | ((uint32_t)sl[ny][2 * kp + 1] << 16);
        size_t o = (size_t)(n0 + ny) * K + k0 + 2 * kp;
        *(uint32_t*)(DH + o) = ph;
        *(uint32_t*)(DL + o) = pl;
    }
}

// ---------------- HMMA grouped GEMM (bf16x3 split) --------------------------
constexpr int BM = 128, BN = 128, BK = 64;
constexpr int SPLIT_SZ = BM * BK * 2;            // 16384 bytes (BM==BN)
constexpr int STAGE_SZ = 4 * SPLIT_SZ;           // Ah, Al, Bh, Bl = 65536
constexpr int SMEM_BYTES = 2 * STAGE_SZ;         // 131072

template <int K, bool FUSED>
__global__ __launch_bounds__(256) void moe_gemm_hmma(
    const bf16* __restrict__ Ah, const bf16* __restrict__ Al,
    const bf16* __restrict__ Bh, const bf16* __restrict__ Bl,
    float* __restrict__ Cout,
    bf16* __restrict__ Hh, bf16* __restrict__ Hl,
    const void* __restrict__ tpe)
{
    const int e = blockIdx.z;
    int off, cnt;
    load_offsets(tpe, e, off, cnt);
    const int m0 = blockIdx.y * BM;
    if (m0 >= cnt) return;
    const int n0 = blockIdx.x * (FUSED ? 64 : 128);

    extern __shared__ char smem[];
    const uint32_t sbase = smem_u32(smem);
    const int tid = threadIdx.x, wid = tid >> 5, lane = tid & 31;

    const size_t bstride = (size_t)(FUSED ? 2 * INTER : HIDDEN) * K;
    const bf16* Ahg = Ah + (size_t)off * K;
    const bf16* Alg = Al + (size_t)off * K;
    const bf16* Bhg = Bh + (size_t)e * bstride;
    const bf16* Blg = Bl + (size_t)e * bstride;

    // Warp tile: 64m x 32n, warps 2(m) x 4(n)
    const int wm = (wid & 1) * 64;
    const int wn = (wid >> 1) * 32;
    const int g = lane >> 3, r8 = lane & 7;

    // ldmatrix per-lane byte offsets (unswizzled; swizzle applied per use)
    int a_base[4], b_base[2];
#pragma unroll
    for (int mi = 0; mi < 4; mi++)
        a_base[mi] = (wm + mi * 16 + r8 + (g & 1) * 8) * 128 + (g >> 1) * 16;
#pragma unroll
    for (int ni2 = 0; ni2 < 2; ni2++)
        b_base[ni2] = (wn + ni2 * 16 + r8 + (g >> 1) * 8) * 128 + (g & 1) * 16;

    // cooperative load indices: one 16B unit per (thread, iter)
    const int ld_row = tid >> 3;            // 0..31 then +32 each iter
    const int ld_ks  = tid & 7;             // 16B unit within 128B row

    float acc[4][4][4];
#pragma unroll
    for (int mi = 0; mi < 4; mi++)
#pragma unroll
        for (int ni = 0; ni < 4; ni++)
#pragma unroll
            for (int q = 0; q < 4; q++) acc[mi][ni][q] = 0.0f;

    constexpr int NCH = K / BK;

    auto load_stage = [&](int c) {
        const uint32_t st = sbase + (c & 1) * STAGE_SZ;
        const int k0 = c * BK;
#pragma unroll
        for (int i = 0; i < 4; ++i) {
            int row = ld_row + i * 32;
            uint32_t so = SW128(row * 128 + ld_ks * 16);
            // A (ragged rows -> zero-fill)
            int gr = m0 + row;
            int nb = (gr < cnt) ? 16 : 0;
            int grc = (gr < cnt) ? gr : 0;
            size_t goA = (size_t)grc * K + k0 + ld_ks * 8;
            cp16(st + so, Ahg + goA, nb);
            cp16(st + SPLIT_SZ + so, Alg + goA, nb);
            // B
            int grow = FUSED ? (n0 + (row & 63) + ((row >= 64) ? INTER : 0))
                             : (n0 + row);
            size_t goB = (size_t)grow * K + k0 + ld_ks * 8;
            cp16(st + 2 * SPLIT_SZ + so, Bhg + goB, 16);
            cp16(st + 3 * SPLIT_SZ + so, Blg + goB, 16);
        }
        asm volatile("cp.async.commit_group;" ::: "memory");
    };

    load_stage(0);

    for (int c = 0; c < NCH; ++c) {
        if (c + 1 < NCH) load_stage(c + 1);
        if (c + 1 < NCH)
            asm volatile("cp.async.wait_group 1;" ::: "memory");
        else
            asm volatile("cp.async.wait_group 0;" ::: "memory");
        __syncthreads();

        const uint32_t st = sbase + (c & 1) * STAGE_SZ;
        const uint32_t sAh = st, sAl = st + SPLIT_SZ;
        const uint32_t sBh = st + 2 * SPLIT_SZ, sBl = st + 3 * SPLIT_SZ;

#pragma unroll
        for (int kk = 0; kk < 4; ++kk) {
            const int kb = kk * 32;   // byte offset of this k16 step
            uint32_t ah[4][4], al[4][4], bh[4][2], bl[4][2];
#pragma unroll
            for (int mi = 0; mi < 4; mi++) {
                ldmx4(ah[mi], sAh + SW128(a_base[mi] + kb));
                ldmx4(al[mi], sAl + SW128(a_base[mi] + kb));
            }
#pragma unroll
            for (int ni2 = 0; ni2 < 2; ni2++) {
                uint32_t t[4];
                ldmx4(t, sBh + SW128(b_base[ni2] + kb));
                bh[ni2 * 2][0] = t[0]; bh[ni2 * 2][1] = t[1];
                bh[ni2 * 2 + 1][0] = t[2]; bh[ni2 * 2 + 1][1] = t[3];
                ldmx4(t, sBl + SW128(b_base[ni2] + kb));
                bl[ni2 * 2][0] = t[0]; bl[ni2 * 2][1] = t[1];
                bl[ni2 * 2 + 1][0] = t[2]; bl[ni2 * 2 + 1][1] = t[3];
            }
#pragma unroll
            for (int mi = 0; mi < 4; mi++)
#pragma unroll
                for (int ni = 0; ni < 4; ni++) {
                    mma16816(acc[mi][ni], ah[mi], bh[ni]);
                    mma16816(acc[mi][ni], ah[mi], bl[ni]);
                    mma16816(acc[mi][ni], al[mi], bh[ni]);
                }
        }
        __syncthreads();
    }

    // ---------------- epilogue: stage accum through SMEM ----------------
    float* shf = (float*)smem;   // [128][132] fp32, 67.6 KB (fits in stages)
    const int crow = wm + (lane >> 2);
    const int ccol0 = wn + (lane & 3) * 2;
#pragma unroll
    for (int mi = 0; mi < 4; mi++)
#pragma unroll
        for (int ni = 0; ni < 4; ni++) {
            int rr = crow + mi * 16, cc = ccol0 + ni * 8;
            *(float2*)&shf[rr * 132 + cc]       = make_float2(acc[mi][ni][0], acc[mi][ni][1]);
            *(float2*)&shf[(rr + 8) * 132 + cc] = make_float2(acc[mi][ni][2], acc[mi][ni][3]);
        }
    __syncthreads();

    if (FUSED) {
        // cols [0,64) = gate(n0+j), [64,128) = up(n0+j); h = silu(g)*u
        for (int idx = tid; idx < 128 * 64; idx += 256) {
            int rr = idx >> 6, j = idx & 63;
            if (m0 + rr >= cnt) continue;
            float gate = shf[rr * 132 + j];
            float up   = shf[rr * 132 + 64 + j];
            float h = up * gate / (1.0f + __expf(-gate));
            unsigned short hh, hl;
            split_bf16(h, hh, hl);
            size_t gof = (size_t)(off + m0 + rr) * INTER + n0 + j;
            *(unsigned short*)(Hh + gof) = hh;
            *(unsigned short*)(Hl + gof) = hl;
        }
    } else {
        for (int idx = tid; idx < 128 * 32; idx += 256) {
            int rr = idx >> 5, cu = idx & 31;
            if (m0 + rr >= cnt) continue;
            *(float4*)(Cout + (size_t)(off + m0 + rr) * HIDDEN + n0 + cu * 4) =
                *(float4*)&shf[rr * 132 + cu * 4];
        }
    }
}

// ---------------- launch -----------------------------------------------------
extern "C" void kernel_launch(void* const* d_in, const int* in_sizes, int n_in,
                              void* d_out, int out_size) {
    const float* x    = (const float*)d_in[0];
    const float* w1   = (const float*)d_in[1];
    const float* w2   = (const float*)d_in[2];
    const void*  tpe  = d_in[3];
    float* out = (float*)d_out;

    bf16 *xh, *xl, *w1h, *w1l, *w2h, *w2l, *hh, *hl;
    cudaGetSymbolAddress((void**)&xh,  g_xh);
    cudaGetSymbolAddress((void**)&xl,  g_xl);
    cudaGetSymbolAddress((void**)&w1h, g_w1h);
    cudaGetSymbolAddress((void**)&w1l, g_w1l);
    cudaGetSymbolAddress((void**)&w2h, g_w2h);
    cudaGetSymbolAddress((void**)&w2l, g_w2l);
    cudaGetSymbolAddress((void**)&hh,  g_hh);
    cudaGetSymbolAddress((void**)&hl,  g_hl);

    convert_split<<<(TOKENS * HIDDEN / 4 + 255) / 256, 256>>>(x, xh, xl, TOKENS * HIDDEN / 4);
    convert_split_t<<<dim3(2 * INTER / 32, HIDDEN / 32, NEXP), 256>>>(w1, w1h, w1l, HIDDEN, 2 * INTER);
    convert_split_t<<<dim3(HIDDEN / 32, INTER / 32, NEXP), 256>>>(w2, w2h, w2l, INTER, HIDDEN);

    cudaFuncSetAttribute(moe_gemm_hmma<HIDDEN, true>,
                         cudaFuncAttributeMaxDynamicSharedMemorySize, SMEM_BYTES);
    cudaFuncSetAttribute(moe_gemm_hmma<INTER, false>,
                         cudaFuncAttributeMaxDynamicSharedMemorySize, SMEM_BYTES);

    // GEMM1 (fused swiglu): each n-tile covers 64 gate + 64 up columns
    moe_gemm_hmma<HIDDEN, true><<<dim3(INTER / 64, TOKENS / 128, NEXP), 256, SMEM_BYTES>>>(
        xh, xl, w1h, w1l, nullptr, hh, hl, tpe);
    // GEMM2
    moe_gemm_hmma<INTER, false><<<dim3(HIDDEN / 128, TOKENS / 128, NEXP), 256, SMEM_BYTES>>>(
        hh, hl, w2h, w2l, out, nullptr, nullptr, tpe);
}

// round 4
// speedup vs baseline: 4.4837x; 1.6071x over previous
#include <cuda_runtime.h>
#include <cuda_fp16.h>
#include <cstdint>

using f16 = __half;

constexpr int HIDDEN = 1024;
constexpr int INTER  = 1408;
constexpr int NEXP   = 8;
constexpr int TOKENS = 8192;

// ---------------- scratch (device globals; no allocation allowed) ----------
__device__ __align__(256) f16 g_xh[(size_t)TOKENS * HIDDEN];
__device__ __align__(256) f16 g_xl[(size_t)TOKENS * HIDDEN];
__device__ __align__(256) f16 g_w1[(size_t)NEXP * 2 * INTER * HIDDEN];  // [E][N=2816][K=1024]
__device__ __align__(256) f16 g_w2[(size_t)NEXP * HIDDEN * INTER];      // [E][N=1024][K=1408]
__device__ __align__(256) f16 g_hh[(size_t)TOKENS * INTER];
__device__ __align__(256) f16 g_hl[(size_t)TOKENS * INTER];

// ---------------- helpers ---------------------------------------------------
__device__ __forceinline__ void load_offsets(const void* tpe_ptr, int e,
                                             int& off, int& cnt) {
    const int* p32 = (const int*)tpe_ptr;
    int s = 0;
#pragma unroll
    for (int i = 0; i < NEXP; i++) s += p32[i];
    off = 0; cnt = 0;
    if (s == TOKENS) {
#pragma unroll
        for (int i = 0; i < NEXP; i++) {
            int v = p32[i];
            if (i < e)  off += v;
            if (i == e) cnt = v;
        }
    } else {
        const long long* p64 = (const long long*)tpe_ptr;
#pragma unroll
        for (int i = 0; i < NEXP; i++) {
            int v = (int)p64[i];
            if (i < e)  off += v;
            if (i == e) cnt = v;
        }
    }
}

__device__ __forceinline__ uint32_t smem_u32(const void* p) {
    uint32_t a;
    asm("{ .reg .u64 t; cvta.to.shared.u64 t, %1; cvt.u32.u64 %0, t; }"
        : "=r"(a) : "l"(p));
    return a;
}

#define SW128(o) ((o) ^ (((o) >> 3) & 0x70))

__device__ __forceinline__ void cp16(uint32_t s, const void* g, int nbytes) {
    asm volatile("cp.async.cg.shared.global [%0], [%1], 16, %2;"
                 :: "r"(s), "l"(g), "r"(nbytes) : "memory");
}

__device__ __forceinline__ void ldmx4(uint32_t* r, uint32_t addr) {
    asm volatile("ldmatrix.sync.aligned.m8n8.x4.shared.b16 {%0,%1,%2,%3}, [%4];"
                 : "=r"(r[0]), "=r"(r[1]), "=r"(r[2]), "=r"(r[3]) : "r"(addr));
}

__device__ __forceinline__ void mma16816(float* c, const uint32_t* a, const uint32_t* b) {
    asm volatile("mma.sync.aligned.m16n8k16.row.col.f32.f16.f16.f32 "
                 "{%0,%1,%2,%3}, {%4,%5,%6,%7}, {%8,%9}, {%0,%1,%2,%3};"
                 : "+f"(c[0]), "+f"(c[1]), "+f"(c[2]), "+f"(c[3])
                 : "r"(a[0]), "r"(a[1]), "r"(a[2]), "r"(a[3]),
                   "r"(b[0]), "r"(b[1]));
}

__device__ __forceinline__ void split_f16(float v, unsigned short& h, unsigned short& l) {
    f16 hb = __float2half_rn(v);
    f16 lb = __float2half_rn(v - __half2float(hb));
    h = __half_as_ushort(hb);
    l = __half_as_ushort(lb);
}

// ---------------- conversion kernels ---------------------------------------
__global__ __launch_bounds__(256) void convert_split(
    const float* __restrict__ src, f16* __restrict__ dh, f16* __restrict__ dl, int n4)
{
    int i = blockIdx.x * 256 + threadIdx.x;
    if (i >= n4) return;
    float4 v = ((const float4*)src)[i];
    float vv[4] = {v.x, v.y, v.z, v.w};
    unsigned short hh[4], ll[4];
#pragma unroll
    for (int j = 0; j < 4; j++) split_f16(vv[j], hh[j], ll[j]);
    uint2 ph = make_uint2((uint32_t)hh[0] | ((uint32_t)hh[1] << 16),
                          (uint32_t)hh[2] | ((uint32_t)hh[3] << 16));
    uint2 pl = make_uint2((uint32_t)ll[0] | ((uint32_t)ll[1] << 16),
                          (uint32_t)ll[2] | ((uint32_t)ll[3] << 16));
    ((uint2*)dh)[i] = ph;
    ((uint2*)dl)[i] = pl;
}

// transpose: src [E][K][N] f32 -> dst [E][N][K] fp16
__global__ __launch_bounds__(256) void convert_t(
    const float* __restrict__ src, f16* __restrict__ dst, int K, int N)
{
    __shared__ unsigned short sh[32][33];
    const float* S = src + (size_t)blockIdx.z * K * N;
    f16* D = dst + (size_t)blockIdx.z * K * N;
    int n0 = blockIdx.x * 32, k0 = blockIdx.y * 32;
    int tx = threadIdx.x & 31, ty = threadIdx.x >> 5;
#pragma unroll
    for (int r = ty; r < 32; r += 8) {
        float v = S[(size_t)(k0 + r) * N + n0 + tx];
        sh[tx][r] = __half_as_ushort(__float2half_rn(v));
    }
    __syncthreads();
    int kp = threadIdx.x & 15, nyb = threadIdx.x >> 4;
#pragma unroll
    for (int ny = nyb; ny < 32; ny += 16) {
        uint32_t p = (uint32_t)sh[ny][2 * kp] | ((uint32_t)sh[ny][2 * kp + 1] << 16);
        *(uint32_t*)(D + (size_t)(n0 + ny) * K + k0 + 2 * kp) = p;
    }
}

// ---------------- HMMA grouped GEMM (fp16, A-split 2-product) ---------------
constexpr int BM = 128, BN = 128, BK = 64;
constexpr int SPLIT_SZ = BM * BK * 2;            // 16384 bytes
constexpr int STAGE_SZ = 3 * SPLIT_SZ;           // Ah, Al, B = 49152
constexpr int SMEM_BYTES = 2 * STAGE_SZ;         // 98304 -> 2 CTAs/SM

template <int K, bool FUSED>
__global__ __launch_bounds__(256, 2) void moe_gemm_hmma(
    const f16* __restrict__ Ah, const f16* __restrict__ Al,
    const f16* __restrict__ B,
    float* __restrict__ Cout,
    f16* __restrict__ Hh, f16* __restrict__ Hl,
    const void* __restrict__ tpe)
{
    const int e = blockIdx.z;
    int off, cnt;
    load_offsets(tpe, e, off, cnt);
    const int m0 = blockIdx.y * BM;
    if (m0 >= cnt) return;
    const int n0 = blockIdx.x * (FUSED ? 64 : 128);

    extern __shared__ char smem[];
    const uint32_t sbase = smem_u32(smem);
    const int tid = threadIdx.x, wid = tid >> 5, lane = tid & 31;

    const size_t bstride = (size_t)(FUSED ? 2 * INTER : HIDDEN) * K;
    const f16* Ahg = Ah + (size_t)off * K;
    const f16* Alg = Al + (size_t)off * K;
    const f16* Bg  = B + (size_t)e * bstride;

    // Warp tile: 64m x 32n, warps 2(m) x 4(n)
    const int wm = (wid & 1) * 64;
    const int wn = (wid >> 1) * 32;
    const int g = lane >> 3, r8 = lane & 7;

    int a_base[4], b_base[2];
#pragma unroll
    for (int mi = 0; mi < 4; mi++)
        a_base[mi] = (wm + mi * 16 + r8 + (g & 1) * 8) * 128 + (g >> 1) * 16;
#pragma unroll
    for (int ni2 = 0; ni2 < 2; ni2++)
        b_base[ni2] = (wn + ni2 * 16 + r8 + (g >> 1) * 8) * 128 + (g & 1) * 16;

    const int ld_row = tid >> 3;            // 0..31, +32 per iter
    const int ld_ks  = tid & 7;

    float acc[4][4][4];
#pragma unroll
    for (int mi = 0; mi < 4; mi++)
#pragma unroll
        for (int ni = 0; ni < 4; ni++)
#pragma unroll
            for (int q = 0; q < 4; q++) acc[mi][ni][q] = 0.0f;

    constexpr int NCH = K / BK;

    auto load_stage = [&](int c) {
        const uint32_t st = sbase + (c & 1) * STAGE_SZ;
        const int k0 = c * BK;
#pragma unroll
        for (int i = 0; i < 4; ++i) {
            int row = ld_row + i * 32;
            uint32_t so = SW128(row * 128 + ld_ks * 16);
            int gr = m0 + row;
            int nb = (gr < cnt) ? 16 : 0;
            int grc = (gr < cnt) ? gr : 0;
            size_t goA = (size_t)grc * K + k0 + ld_ks * 8;
            cp16(st + so, Ahg + goA, nb);
            cp16(st + SPLIT_SZ + so, Alg + goA, nb);
            int grow = FUSED ? (n0 + (row & 63) + ((row >= 64) ? INTER : 0))
                             : (n0 + row);
            size_t goB = (size_t)grow * K + k0 + ld_ks * 8;
            cp16(st + 2 * SPLIT_SZ + so, Bg + goB, 16);
        }
        asm volatile("cp.async.commit_group;" ::: "memory");
    };

    load_stage(0);

    for (int c = 0; c < NCH; ++c) {
        if (c + 1 < NCH) {
            load_stage(c + 1);
            asm volatile("cp.async.wait_group 1;" ::: "memory");
        } else {
            asm volatile("cp.async.wait_group 0;" ::: "memory");
        }
        __syncthreads();

        const uint32_t st = sbase + (c & 1) * STAGE_SZ;
        const uint32_t sAh = st, sAl = st + SPLIT_SZ, sB = st + 2 * SPLIT_SZ;

#pragma unroll
        for (int kk = 0; kk < 4; ++kk) {
            const int kb = kk * 32;
            uint32_t b[4][2];
#pragma unroll
            for (int ni2 = 0; ni2 < 2; ni2++) {
                uint32_t t[4];
                ldmx4(t, sB + SW128(b_base[ni2] + kb));
                b[ni2 * 2][0] = t[0]; b[ni2 * 2][1] = t[1];
                b[ni2 * 2 + 1][0] = t[2]; b[ni2 * 2 + 1][1] = t[3];
            }
#pragma unroll
            for (int mi = 0; mi < 4; mi++) {
                uint32_t ah[4], al[4];
                ldmx4(ah, sAh + SW128(a_base[mi] + kb));
                ldmx4(al, sAl + SW128(a_base[mi] + kb));
#pragma unroll
                for (int ni = 0; ni < 4; ni++) {
                    mma16816(acc[mi][ni], ah, b[ni]);
                    mma16816(acc[mi][ni], al, b[ni]);
                }
            }
        }
        __syncthreads();
    }

    // ---------------- epilogue: stage accum through SMEM ----------------
    float* shf = (float*)smem;   // [128][132] fp32 = 67.6 KB
    const int crow = wm + (lane >> 2);
    const int ccol0 = wn + (lane & 3) * 2;
#pragma unroll
    for (int mi = 0; mi < 4; mi++)
#pragma unroll
        for (int ni = 0; ni < 4; ni++) {
            int rr = crow + mi * 16, cc = ccol0 + ni * 8;
            *(float2*)&shf[rr * 132 + cc]       = make_float2(acc[mi][ni][0], acc[mi][ni][1]);
            *(float2*)&shf[(rr + 8) * 132 + cc] = make_float2(acc[mi][ni][2], acc[mi][ni][3]);
        }
    __syncthreads();

    if (FUSED) {
        // cols [0,64) = gate(n0+j), [64,128) = up(n0+j); h = silu(g)*u
        for (int idx = tid; idx < 128 * 32; idx += 256) {
            int rr = idx >> 5, j = (idx & 31) * 2;
            if (m0 + rr >= cnt) continue;
            float g0 = shf[rr * 132 + j],     g1 = shf[rr * 132 + j + 1];
            float u0 = shf[rr * 132 + 64 + j], u1 = shf[rr * 132 + 64 + j + 1];
            float h0 = u0 * g0 / (1.0f + __expf(-g0));
            float h1 = u1 * g1 / (1.0f + __expf(-g1));
            unsigned short h0h, h0l, h1h, h1l;
            split_f16(h0, h0h, h0l);
            split_f16(h1, h1h, h1l);
            size_t gof = (size_t)(off + m0 + rr) * INTER + n0 + j;
            *(uint32_t*)(Hh + gof) = (uint32_t)h0h | ((uint32_t)h1h << 16);
            *(uint32_t*)(Hl + gof) = (uint32_t)h0l | ((uint32_t)h1l << 16);
        }
    } else {
        for (int idx = tid; idx < 128 * 32; idx += 256) {
            int rr = idx >> 5, cu = idx & 31;
            if (m0 + rr >= cnt) continue;
            *(float4*)(Cout + (size_t)(off + m0 + rr) * HIDDEN + n0 + cu * 4) =
                *(float4*)&shf[rr * 132 + cu * 4];
        }
    }
}

// ---------------- launch -----------------------------------------------------
extern "C" void kernel_launch(void* const* d_in, const int* in_sizes, int n_in,
                              void* d_out, int out_size) {
    const float* x    = (const float*)d_in[0];
    const float* w1   = (const float*)d_in[1];
    const float* w2   = (const float*)d_in[2];
    const void*  tpe  = d_in[3];
    float* out = (float*)d_out;

    f16 *xh, *xl, *w1f, *w2f, *hh, *hl;
    cudaGetSymbolAddress((void**)&xh,  g_xh);
    cudaGetSymbolAddress((void**)&xl,  g_xl);
    cudaGetSymbolAddress((void**)&w1f, g_w1);
    cudaGetSymbolAddress((void**)&w2f, g_w2);
    cudaGetSymbolAddress((void**)&hh,  g_hh);
    cudaGetSymbolAddress((void**)&hl,  g_hl);

    convert_split<<<(TOKENS * HIDDEN / 4 + 255) / 256, 256>>>(x, xh, xl, TOKENS * HIDDEN / 4);
    convert_t<<<dim3(2 * INTER / 32, HIDDEN / 32, NEXP), 256>>>(w1, w1f, HIDDEN, 2 * INTER);
    convert_t<<<dim3(HIDDEN / 32, INTER / 32, NEXP), 256>>>(w2, w2f, INTER, HIDDEN);

    cudaFuncSetAttribute(moe_gemm_hmma<HIDDEN, true>,
                         cudaFuncAttributeMaxDynamicSharedMemorySize, SMEM_BYTES);
    cudaFuncSetAttribute(moe_gemm_hmma<INTER, false>,
                         cudaFuncAttributeMaxDynamicSharedMemorySize, SMEM_BYTES);

    // GEMM1 (fused swiglu): each n-tile covers 64 gate + 64 up columns
    moe_gemm_hmma<HIDDEN, true><<<dim3(INTER / 64, TOKENS / 128, NEXP), 256, SMEM_BYTES>>>(
        xh, xl, w1f, nullptr, hh, hl, tpe);
    // GEMM2
    moe_gemm_hmma<INTER, false><<<dim3(HIDDEN / 128, TOKENS / 128, NEXP), 256, SMEM_BYTES>>>(
        hh, hl, w2f, out, nullptr, nullptr, tpe);
}

// round 5
// speedup vs baseline: 6.8833x; 1.5352x over previous
#include <cuda_runtime.h>
#include <cuda_fp16.h>
#include <cstdint>

using f16 = __half;

constexpr int HIDDEN = 1024;
constexpr int INTER  = 1408;
constexpr int NEXP   = 8;
constexpr int TOKENS = 8192;

// ---------------- scratch (device globals; no allocation allowed) ----------
__device__ __align__(256) f16 g_x[(size_t)TOKENS * HIDDEN];
__device__ __align__(256) f16 g_w1[(size_t)NEXP * 2 * INTER * HIDDEN];  // [E][N=2816][K=1024]
__device__ __align__(256) f16 g_w2[(size_t)NEXP * HIDDEN * INTER];      // [E][N=1024][K=1408]
__device__ __align__(256) f16 g_h[(size_t)TOKENS * INTER];

// ---------------- helpers ---------------------------------------------------
__device__ __forceinline__ void load_offsets(const void* tpe_ptr, int e,
                                             int& off, int& cnt) {
    const int* p32 = (const int*)tpe_ptr;
    int s = 0;
#pragma unroll
    for (int i = 0; i < NEXP; i++) s += p32[i];
    off = 0; cnt = 0;
    if (s == TOKENS) {
#pragma unroll
        for (int i = 0; i < NEXP; i++) {
            int v = p32[i];
            if (i < e)  off += v;
            if (i == e) cnt = v;
        }
    } else {
        const long long* p64 = (const long long*)tpe_ptr;
#pragma unroll
        for (int i = 0; i < NEXP; i++) {
            int v = (int)p64[i];
            if (i < e)  off += v;
            if (i == e) cnt = v;
        }
    }
}

__device__ __forceinline__ uint32_t smem_u32(const void* p) {
    uint32_t a;
    asm("{ .reg .u64 t; cvta.to.shared.u64 t, %1; cvt.u32.u64 %0, t; }"
        : "=r"(a) : "l"(p));
    return a;
}

#define SW128(o) ((o) ^ (((o) >> 3) & 0x70))

__device__ __forceinline__ void cp16(uint32_t s, const void* g, int nbytes) {
    asm volatile("cp.async.cg.shared.global [%0], [%1], 16, %2;"
                 :: "r"(s), "l"(g), "r"(nbytes) : "memory");
}

__device__ __forceinline__ void ldmx4(uint32_t* r, uint32_t addr) {
    asm volatile("ldmatrix.sync.aligned.m8n8.x4.shared.b16 {%0,%1,%2,%3}, [%4];"
                 : "=r"(r[0]), "=r"(r[1]), "=r"(r[2]), "=r"(r[3]) : "r"(addr));
}

__device__ __forceinline__ void mma16816(float* c, const uint32_t* a, const uint32_t* b) {
    asm volatile("mma.sync.aligned.m16n8k16.row.col.f32.f16.f16.f32 "
                 "{%0,%1,%2,%3}, {%4,%5,%6,%7}, {%8,%9}, {%0,%1,%2,%3};"
                 : "+f"(c[0]), "+f"(c[1]), "+f"(c[2]), "+f"(c[3])
                 : "r"(a[0]), "r"(a[1]), "r"(a[2]), "r"(a[3]),
                   "r"(b[0]), "r"(b[1]));
}

// ---------------- conversion kernels ---------------------------------------
__global__ __launch_bounds__(256) void convert_f16(
    const float* __restrict__ src, f16* __restrict__ dst, int n4)
{
    int i = blockIdx.x * 256 + threadIdx.x;
    if (i >= n4) return;
    float4 v = ((const float4*)src)[i];
    __half2 a = __floats2half2_rn(v.x, v.y);
    __half2 b = __floats2half2_rn(v.z, v.w);
    ((uint2*)dst)[i] = make_uint2(*(uint32_t*)&a, *(uint32_t*)&b);
}

// transpose: src [E][K][N] f32 -> dst [E][N][K] fp16
__global__ __launch_bounds__(256) void convert_t(
    const float* __restrict__ src, f16* __restrict__ dst, int K, int N)
{
    __shared__ unsigned short sh[32][33];
    const float* S = src + (size_t)blockIdx.z * K * N;
    f16* D = dst + (size_t)blockIdx.z * K * N;
    int n0 = blockIdx.x * 32, k0 = blockIdx.y * 32;
    int tx = threadIdx.x & 31, ty = threadIdx.x >> 5;
#pragma unroll
    for (int r = ty; r < 32; r += 8) {
        float v = S[(size_t)(k0 + r) * N + n0 + tx];
        sh[tx][r] = __half_as_ushort(__float2half_rn(v));
    }
    __syncthreads();
    int kp = threadIdx.x & 15, nyb = threadIdx.x >> 4;
#pragma unroll
    for (int ny = nyb; ny < 32; ny += 16) {
        uint32_t p = (uint32_t)sh[ny][2 * kp] | ((uint32_t)sh[ny][2 * kp + 1] << 16);
        *(uint32_t*)(D + (size_t)(n0 + ny) * K + k0 + 2 * kp) = p;
    }
}

// ---------------- HMMA grouped GEMM (pure fp16, fp32 accum) -----------------
constexpr int BM = 128, BN = 128, BK = 64;
constexpr int TILE_SZ = BM * BK * 2;             // 16384 bytes (A or B)
constexpr int STAGE_SZ = 2 * TILE_SZ;            // A + B = 32768
constexpr int NSTAGE = 3;
constexpr int SMEM_BYTES = NSTAGE * STAGE_SZ;    // 98304 -> 2 CTAs/SM

template <int K, bool FUSED>
__global__ __launch_bounds__(256, 2) void moe_gemm_hmma(
    const f16* __restrict__ A, const f16* __restrict__ B,
    float* __restrict__ Cout, f16* __restrict__ H,
    const void* __restrict__ tpe)
{
    const int e = blockIdx.z;
    int off, cnt;
    load_offsets(tpe, e, off, cnt);
    const int m0 = blockIdx.y * BM;
    if (m0 >= cnt) return;
    const int n0 = blockIdx.x * (FUSED ? 64 : 128);

    extern __shared__ char smem[];
    const uint32_t sbase = smem_u32(smem);
    const int tid = threadIdx.x, wid = tid >> 5, lane = tid & 31;

    const size_t bstride = (size_t)(FUSED ? 2 * INTER : HIDDEN) * K;
    const f16* Ag = A + (size_t)off * K;
    const f16* Bg = B + (size_t)e * bstride;

    // Warp tile: 64m x 32n, warps 2(m) x 4(n)
    const int wm = (wid & 1) * 64;
    const int wn = (wid >> 1) * 32;
    const int g = lane >> 3, r8 = lane & 7;

    int a_base[4], b_base[2];
#pragma unroll
    for (int mi = 0; mi < 4; mi++)
        a_base[mi] = (wm + mi * 16 + r8 + (g & 1) * 8) * 128 + (g >> 1) * 16;
#pragma unroll
    for (int ni2 = 0; ni2 < 2; ni2++)
        b_base[ni2] = (wn + ni2 * 16 + r8 + (g >> 1) * 8) * 128 + (g & 1) * 16;

    const int ld_row = tid >> 3;            // 0..31, +32 per iter
    const int ld_ks  = tid & 7;

    float acc[4][4][4];
#pragma unroll
    for (int mi = 0; mi < 4; mi++)
#pragma unroll
        for (int ni = 0; ni < 4; ni++)
#pragma unroll
            for (int q = 0; q < 4; q++) acc[mi][ni][q] = 0.0f;

    constexpr int NCH = K / BK;

    auto load_stage = [&](int c) {
        const uint32_t st = sbase + (c % NSTAGE) * STAGE_SZ;
        const int k0 = c * BK;
#pragma unroll
        for (int i = 0; i < 4; ++i) {
            int row = ld_row + i * 32;
            uint32_t so = SW128(row * 128 + ld_ks * 16);
            int gr = m0 + row;
            int nb = (gr < cnt) ? 16 : 0;
            int grc = (gr < cnt) ? gr : 0;
            size_t goA = (size_t)grc * K + k0 + ld_ks * 8;
            cp16(st + so, Ag + goA, nb);
            int grow = FUSED ? (n0 + (row & 63) + ((row >= 64) ? INTER : 0))
                             : (n0 + row);
            size_t goB = (size_t)grow * K + k0 + ld_ks * 8;
            cp16(st + TILE_SZ + so, Bg + goB, 16);
        }
        asm volatile("cp.async.commit_group;" ::: "memory");
    };

    load_stage(0);
    if (NCH > 1) load_stage(1);

    for (int c = 0; c < NCH; ++c) {
        if (c + 2 < NCH) {
            load_stage(c + 2);
            asm volatile("cp.async.wait_group 2;" ::: "memory");
        } else if (c + 1 < NCH) {
            asm volatile("cp.async.wait_group 1;" ::: "memory");
        } else {
            asm volatile("cp.async.wait_group 0;" ::: "memory");
        }
        __syncthreads();

        const uint32_t st = sbase + (c % NSTAGE) * STAGE_SZ;
        const uint32_t sA = st, sB = st + TILE_SZ;

#pragma unroll
        for (int kk = 0; kk < 4; ++kk) {
            const int kb = kk * 32;
            uint32_t b[4][2];
#pragma unroll
            for (int ni2 = 0; ni2 < 2; ni2++) {
                uint32_t t[4];
                ldmx4(t, sB + SW128(b_base[ni2] + kb));
                b[ni2 * 2][0] = t[0]; b[ni2 * 2][1] = t[1];
                b[ni2 * 2 + 1][0] = t[2]; b[ni2 * 2 + 1][1] = t[3];
            }
#pragma unroll
            for (int mi = 0; mi < 4; mi++) {
                uint32_t a[4];
                ldmx4(a, sA + SW128(a_base[mi] + kb));
#pragma unroll
                for (int ni = 0; ni < 4; ni++)
                    mma16816(acc[mi][ni], a, b[ni]);
            }
        }
        __syncthreads();
    }

    // ---------------- epilogue: stage accum through SMEM ----------------
    float* shf = (float*)smem;   // [128][132] fp32 = 67.6 KB (< 96 KB)
    const int crow = wm + (lane >> 2);
    const int ccol0 = wn + (lane & 3) * 2;
#pragma unroll
    for (int mi = 0; mi < 4; mi++)
#pragma unroll
        for (int ni = 0; ni < 4; ni++) {
            int rr = crow + mi * 16, cc = ccol0 + ni * 8;
            *(float2*)&shf[rr * 132 + cc]       = make_float2(acc[mi][ni][0], acc[mi][ni][1]);
            *(float2*)&shf[(rr + 8) * 132 + cc] = make_float2(acc[mi][ni][2], acc[mi][ni][3]);
        }
    __syncthreads();

    if (FUSED) {
        // cols [0,64) = gate(n0+j), [64,128) = up(n0+j); h = silu(g)*u
        for (int idx = tid; idx < 128 * 32; idx += 256) {
            int rr = idx >> 5, j = (idx & 31) * 2;
            if (m0 + rr >= cnt) continue;
            float g0 = shf[rr * 132 + j],      g1 = shf[rr * 132 + j + 1];
            float u0 = shf[rr * 132 + 64 + j], u1 = shf[rr * 132 + 64 + j + 1];
            float h0 = u0 * g0 / (1.0f + __expf(-g0));
            float h1 = u1 * g1 / (1.0f + __expf(-g1));
            __half2 hp = __floats2half2_rn(h0, h1);
            *(uint32_t*)(H + (size_t)(off + m0 + rr) * INTER + n0 + j) =
                *(uint32_t*)&hp;
        }
    } else {
        for (int idx = tid; idx < 128 * 32; idx += 256) {
            int rr = idx >> 5, cu = idx & 31;
            if (m0 + rr >= cnt) continue;
            *(float4*)(Cout + (size_t)(off + m0 + rr) * HIDDEN + n0 + cu * 4) =
                *(float4*)&shf[rr * 132 + cu * 4];
        }
    }
}

// ---------------- launch -----------------------------------------------------
extern "C" void kernel_launch(void* const* d_in, const int* in_sizes, int n_in,
                              void* d_out, int out_size) {
    const float* x    = (const float*)d_in[0];
    const float* w1   = (const float*)d_in[1];
    const float* w2   = (const float*)d_in[2];
    const void*  tpe  = d_in[3];
    float* out = (float*)d_out;

    f16 *xf, *w1f, *w2f, *hf;
    cudaGetSymbolAddress((void**)&xf,  g_x);
    cudaGetSymbolAddress((void**)&w1f, g_w1);
    cudaGetSymbolAddress((void**)&w2f, g_w2);
    cudaGetSymbolAddress((void**)&hf,  g_h);

    convert_f16<<<(TOKENS * HIDDEN / 4 + 255) / 256, 256>>>(x, xf, TOKENS * HIDDEN / 4);
    convert_t<<<dim3(2 * INTER / 32, HIDDEN / 32, NEXP), 256>>>(w1, w1f, HIDDEN, 2 * INTER);
    convert_t<<<dim3(HIDDEN / 32, INTER / 32, NEXP), 256>>>(w2, w2f, INTER, HIDDEN);

    cudaFuncSetAttribute(moe_gemm_hmma<HIDDEN, true>,
                         cudaFuncAttributeMaxDynamicSharedMemorySize, SMEM_BYTES);
    cudaFuncSetAttribute(moe_gemm_hmma<INTER, false>,
                         cudaFuncAttributeMaxDynamicSharedMemorySize, SMEM_BYTES);

    // GEMM1 (fused swiglu): each n-tile covers 64 gate + 64 up columns
    moe_gemm_hmma<HIDDEN, true><<<dim3(INTER / 64, TOKENS / 128, NEXP), 256, SMEM_BYTES>>>(
        xf, w1f, nullptr, hf, tpe);
    // GEMM2
    moe_gemm_hmma<INTER, false><<<dim3(HIDDEN / 128, TOKENS / 128, NEXP), 256, SMEM_BYTES>>>(
        hf, w2f, out, nullptr, tpe);
}